// round 9
// baseline (speedup 1.0000x reference)
#include <cuda_runtime.h>
#include <cuda_fp16.h>
#include <math_constants.h>

#define NN   50000
#define NE   800000
#define NET  (NE + NN)          // 850000 edges incl. self loops
#define FIN  128
#define FHID 128
#define FOUT 64
#define NEG  0.2f

// ---------------- scratch (static device globals; no allocation) ----------------
__device__ __half g_h1h[NN * FHID];     // fp16 h layer1
__device__ __half g_acc1h[NN * FHID];   // fp16 layer1 out / layer2 in
__device__ __half g_h2h[NN * FOUT];     // fp16 h layer2
__device__ __half g_w1t[FHID * FIN];    // W1^T fp16  [n][k]
__device__ __half g_w2t[FOUT * FHID];   // W2^T fp16  [n][k]
__device__ float  g_as[NN];
__device__ float  g_ad[NN];
__device__ int    g_cnt[NN];
__device__ int    g_off[NN + 1];
__device__ int    g_rank[NE];
__device__ int    g_srcA[NET];

// ================= mma.m16n8k16 fp16 -> fp32 =================
__device__ __forceinline__ void mma16816(float* c, const unsigned* a,
                                         unsigned b0, unsigned b1) {
    asm volatile(
        "mma.sync.aligned.m16n8k16.row.col.f32.f16.f16.f32 "
        "{%0,%1,%2,%3}, {%4,%5,%6,%7}, {%8,%9}, {%0,%1,%2,%3};\n"
        : "+f"(c[0]), "+f"(c[1]), "+f"(c[2]), "+f"(c[3])
        : "r"(a[0]), "r"(a[1]), "r"(a[2]), "r"(a[3]), "r"(b0), "r"(b1));
}

// ---- convert W1, W2 to fp16 transposed [n][k] ----
__global__ void convW_k(const float* __restrict__ W1, const float* __restrict__ W2,
                        __half* __restrict__ Wt1, __half* __restrict__ Wt2) {
    int i = blockIdx.x * blockDim.x + threadIdx.x;
    if (i < FIN * FHID) {
        int k = i / FHID, n = i % FHID;
        Wt1[n * FIN + k] = __float2half(W1[i]);
    }
    if (i < FHID * FOUT) {
        int k = i / FOUT, n = i % FOUT;
        Wt2[n * FHID + k] = __float2half(W2[i]);
    }
}

// ====== HGEMM: C16[M,BN] = A[M,128] @ Bt^T ; A fp32 (AF16=0) or fp16 (AF16=1) ===
template<int BN, bool AF16>
__global__ void __launch_bounds__(256) hgemm_k(const void* __restrict__ Aptr,
                                               const __half* __restrict__ Bt,  // [BN][128]
                                               __half* __restrict__ C16, int M) {
    constexpr int K = 128, BM = 128, BK = 64;
    constexpr int MT = (BN == 128) ? 2 : 1;
    __shared__ __half Ah[BM][BK + 8];
    __shared__ __half Bs[BN][BK + 8];

    const int tid  = threadIdx.x;
    const int wid  = tid >> 5;
    const int lane = tid & 31;
    const int gr   = lane >> 2;
    const int tig  = lane & 3;
    const int row0 = blockIdx.x * BM;

    int warpRow, warpCol;
    if (BN == 128) { warpRow = (wid >> 1) * 32; warpCol = (wid & 1) * 64; }
    else           { warpRow = wid * 16;        warpCol = 0; }

    float acc[MT][8][4];
#pragma unroll
    for (int mi = 0; mi < MT; mi++)
#pragma unroll
        for (int ni = 0; ni < 8; ni++)
#pragma unroll
            for (int j = 0; j < 4; j++) acc[mi][ni][j] = 0.f;

    for (int kc = 0; kc < K; kc += BK) {
        if (AF16) {
#pragma unroll
            for (int i = tid; i < BM * BK / 8; i += 256) {
                int r = i / (BK / 8), c8 = i % (BK / 8);
                uint4 v = make_uint4(0, 0, 0, 0);
                if (row0 + r < M)
                    v = *(const uint4*)((const __half*)Aptr + (size_t)(row0 + r) * K + kc + c8 * 8);
                *(uint4*)&Ah[r][c8 * 8] = v;
            }
        } else {
#pragma unroll
            for (int i = tid; i < BM * BK / 4; i += 256) {
                int r = i / (BK / 4), c4 = i % (BK / 4);
                float4 v = make_float4(0.f, 0.f, 0.f, 0.f);
                if (row0 + r < M)
                    v = *(const float4*)((const float*)Aptr + (size_t)(row0 + r) * K + kc + c4 * 4);
                __half2 h0 = __floats2half2_rn(v.x, v.y);
                __half2 h1 = __floats2half2_rn(v.z, v.w);
                *(uint2*)&Ah[r][c4 * 4] = make_uint2(*(unsigned*)&h0, *(unsigned*)&h1);
            }
        }
#pragma unroll
        for (int i = tid; i < BN * BK / 8; i += 256) {
            int n = i / (BK / 8), c8 = i % (BK / 8);
            *(uint4*)&Bs[n][c8 * 8] = *(const uint4*)(Bt + (size_t)n * K + kc + c8 * 8);
        }
        __syncthreads();

#pragma unroll
        for (int kk = 0; kk < BK; kk += 16) {
            unsigned a[MT][4];
#pragma unroll
            for (int mi = 0; mi < MT; mi++) {
                int r = warpRow + mi * 16 + gr;
                a[mi][0] = *(unsigned*)&Ah[r][kk + tig * 2];
                a[mi][1] = *(unsigned*)&Ah[r + 8][kk + tig * 2];
                a[mi][2] = *(unsigned*)&Ah[r][kk + tig * 2 + 8];
                a[mi][3] = *(unsigned*)&Ah[r + 8][kk + tig * 2 + 8];
            }
#pragma unroll
            for (int ni = 0; ni < 8; ni++) {
                int n = warpCol + ni * 8 + gr;
                unsigned b0 = *(unsigned*)&Bs[n][kk + tig * 2];
                unsigned b1 = *(unsigned*)&Bs[n][kk + tig * 2 + 8];
#pragma unroll
                for (int mi = 0; mi < MT; mi++) mma16816(acc[mi][ni], a[mi], b0, b1);
            }
        }
        __syncthreads();
    }

#pragma unroll
    for (int mi = 0; mi < MT; mi++)
#pragma unroll
        for (int ni = 0; ni < 8; ni++) {
            int r = row0 + warpRow + mi * 16 + gr;
            int c = warpCol + ni * 8 + tig * 2;
            __half2 lo = __floats2half2_rn(acc[mi][ni][0], acc[mi][ni][1]);
            __half2 hi = __floats2half2_rn(acc[mi][ni][2], acc[mi][ni][3]);
            if (r < M)     *(__half2*)&C16[(size_t)r * BN + c] = lo;
            if (r + 8 < M) *(__half2*)&C16[(size_t)(r + 8) * BN + c] = hi;
        }
}

// ---------------- per-node attention logits from fp16 h ----------------
template<int F>
__global__ void alpha16_k(const __half* __restrict__ h16,
                          const float* __restrict__ a_s,
                          const float* __restrict__ a_d,
                          float* __restrict__ as_out,
                          float* __restrict__ ad_out) {
    int warp = (blockIdx.x * blockDim.x + threadIdx.x) >> 5;
    int lane = threadIdx.x & 31;
    if (warp >= NN) return;
    float ss = 0.f, sd = 0.f;
    if constexpr (F == 128) {
        uint2 q = ((const uint2*)h16)[(size_t)warp * 32 + lane];
        float2 f0 = __half22float2(*(__half2*)&q.x);
        float2 f1 = __half22float2(*(__half2*)&q.y);
        float4 av = ((const float4*)a_s)[lane];
        float4 dv = ((const float4*)a_d)[lane];
        ss = f0.x * av.x + f0.y * av.y + f1.x * av.z + f1.y * av.w;
        sd = f0.x * dv.x + f0.y * dv.y + f1.x * dv.z + f1.y * dv.w;
    } else {
        unsigned q = ((const unsigned*)h16)[(size_t)warp * 32 + lane];
        float2 f = __half22float2(*(__half2*)&q);
        float2 av = ((const float2*)a_s)[lane];
        float2 dv = ((const float2*)a_d)[lane];
        ss = f.x * av.x + f.y * av.y;
        sd = f.x * dv.x + f.y * dv.y;
    }
#pragma unroll
    for (int o = 16; o; o >>= 1) {
        ss += __shfl_down_sync(0xffffffffu, ss, o);
        sd += __shfl_down_sync(0xffffffffu, sd, o);
    }
    if (lane == 0) { as_out[warp] = ss; ad_out[warp] = sd; }
}

// ================= CSR build (dst-sorted adjacency) =================
// 8 edges/thread for MLP=8; rank = per-dst arrival order
__global__ void hist_k(const int* __restrict__ ei, int* __restrict__ cnt,
                       int* __restrict__ rank) {
    int t = blockIdx.x * blockDim.x + threadIdx.x;
    int idx = t * 8;
    if (idx >= NE) return;
    int4 dA = *(const int4*)&ei[NE + idx];
    int4 dB = *(const int4*)&ei[NE + idx + 4];
    int r0 = atomicAdd(&cnt[dA.x], 1);
    int r1 = atomicAdd(&cnt[dA.y], 1);
    int r2 = atomicAdd(&cnt[dA.z], 1);
    int r3 = atomicAdd(&cnt[dA.w], 1);
    int r4 = atomicAdd(&cnt[dB.x], 1);
    int r5 = atomicAdd(&cnt[dB.y], 1);
    int r6 = atomicAdd(&cnt[dB.z], 1);
    int r7 = atomicAdd(&cnt[dB.w], 1);
    *(int4*)&rank[idx]     = make_int4(r0, r1, r2, r3);
    *(int4*)&rank[idx + 4] = make_int4(r4, r5, r6, r7);
}

// single-block scan: off[i+1] = prefix-sum of (cnt[i]+1); also places self loops
__global__ void __launch_bounds__(1024) scan_k(const int* __restrict__ cnt,
                                               int* __restrict__ off,
                                               int* __restrict__ srcA) {
    __shared__ int wsum[32];
    const int tid  = threadIdx.x;
    const int wid  = tid >> 5;
    const int lane = tid & 31;
    int carry = 0;
    if (tid == 0) off[0] = 0;
    for (int base = 0; base < NN; base += 4096) {
        int i0 = base + tid * 4;
        int v0 = 0, v1 = 0, v2 = 0, v3 = 0;
        if (i0 + 3 < NN) {
            int4 c = *(const int4*)&cnt[i0];
            v0 = c.x + 1; v1 = c.y + 1; v2 = c.z + 1; v3 = c.w + 1;
        } else {
            if (i0 + 0 < NN) v0 = cnt[i0 + 0] + 1;
            if (i0 + 1 < NN) v1 = cnt[i0 + 1] + 1;
            if (i0 + 2 < NN) v2 = cnt[i0 + 2] + 1;
            if (i0 + 3 < NN) v3 = cnt[i0 + 3] + 1;
        }
        v1 += v0; v2 += v1; v3 += v2;
        int t = v3;
        int incl = t;
#pragma unroll
        for (int o = 1; o < 32; o <<= 1) {
            int n = __shfl_up_sync(0xffffffffu, incl, o);
            if (lane >= o) incl += n;
        }
        if (lane == 31) wsum[wid] = incl;
        __syncthreads();
        if (wid == 0) {
            int s = wsum[lane];
#pragma unroll
            for (int o = 1; o < 32; o <<= 1) {
                int n = __shfl_up_sync(0xffffffffu, s, o);
                if (lane >= o) s += n;
            }
            wsum[lane] = s;
        }
        __syncthreads();
        int prefix = carry + (wid ? wsum[wid - 1] : 0) + (incl - t);
        // off[i] (exclusive) and self-loop placement at slot off[i]
        if (i0 + 0 < NN) { off[i0 + 1] = prefix + v0; srcA[prefix]      = i0;     }
        if (i0 + 1 < NN) { off[i0 + 2] = prefix + v1; srcA[prefix + v0] = i0 + 1; }
        if (i0 + 2 < NN) { off[i0 + 3] = prefix + v2; srcA[prefix + v1] = i0 + 2; }
        if (i0 + 3 < NN) { off[i0 + 4] = prefix + v3; srcA[prefix + v2] = i0 + 3; }
        carry += wsum[31];
        __syncthreads();
    }
}

// atomic-free scatter: position = off[dst] + 1 + rank ; 8 edges/thread
__global__ void scatter_k(const int* __restrict__ ei, const int* __restrict__ off,
                          const int* __restrict__ rank, int* __restrict__ srcA) {
    int t = blockIdx.x * blockDim.x + threadIdx.x;
    int idx = t * 8;
    if (idx >= NE) return;
    int4 sA  = *(const int4*)&ei[idx];
    int4 sB  = *(const int4*)&ei[idx + 4];
    int4 dA  = *(const int4*)&ei[NE + idx];
    int4 dB  = *(const int4*)&ei[NE + idx + 4];
    int4 rA  = *(const int4*)&rank[idx];
    int4 rB  = *(const int4*)&rank[idx + 4];
    int o0 = off[dA.x], o1 = off[dA.y], o2 = off[dA.z], o3 = off[dA.w];
    int o4 = off[dB.x], o5 = off[dB.y], o6 = off[dB.z], o7 = off[dB.w];
    srcA[o0 + 1 + rA.x] = sA.x;
    srcA[o1 + 1 + rA.y] = sA.y;
    srcA[o2 + 1 + rA.z] = sA.z;
    srcA[o3 + 1 + rA.w] = sA.w;
    srcA[o4 + 1 + rB.x] = sB.x;
    srcA[o5 + 1 + rB.y] = sB.y;
    srcA[o6 + 1 + rB.z] = sB.z;
    srcA[o7 + 1 + rB.w] = sB.w;
}

// ======== fused gather+softmax+aggregate, F=128, fp16 in, fp16 out (+relu) =====
// inner loop unrolled x8 for MLP
__global__ void __launch_bounds__(256) agg128_k(
    const __half* __restrict__ h16,
    const float* __restrict__ as, const float* __restrict__ ad,
    const int* __restrict__ off, const int* __restrict__ srcA,
    const float* __restrict__ bias, __half* __restrict__ out16) {
    int node = (blockIdx.x * blockDim.x + threadIdx.x) >> 5;
    int lane = threadIdx.x & 31;
    if (node >= NN) return;
    int beg = off[node], end = off[node + 1];
    float adn = ad[node];

    const uint2* H = (const uint2*)h16;
    float a0 = 0.f, a1 = 0.f, a2 = 0.f, a3 = 0.f, den = 0.f;

    for (int base = beg; base < end; base += 32) {
        int k = base + lane;
        int s = 0;
        float w = 0.f;
        if (k < end) {
            s = srcA[k];
            float e = as[s] + adn;
            e = e > 0.f ? e : NEG * e;
            w = __expf(e);                  // no max-shift: softmax invariant, |e| small
        }
        den += w;
        int cnt = min(32, end - base);
        int j = 0;
        for (; j + 8 <= cnt; j += 8) {
            int   sj[8]; float wj[8]; uint2 q[8];
#pragma unroll
            for (int u = 0; u < 8; u++) {
                sj[u] = __shfl_sync(0xffffffffu, s, j + u);
                wj[u] = __shfl_sync(0xffffffffu, w, j + u);
            }
#pragma unroll
            for (int u = 0; u < 8; u++) q[u] = H[(size_t)sj[u] * 32 + lane];
#pragma unroll
            for (int u = 0; u < 8; u++) {
                float2 f;
                f = __half22float2(*(__half2*)&q[u].x); a0 += wj[u] * f.x; a1 += wj[u] * f.y;
                f = __half22float2(*(__half2*)&q[u].y); a2 += wj[u] * f.x; a3 += wj[u] * f.y;
            }
        }
        for (; j < cnt; j++) {
            int   sjj = __shfl_sync(0xffffffffu, s, j);
            float wjj = __shfl_sync(0xffffffffu, w, j);
            uint2 q = H[(size_t)sjj * 32 + lane];
            float2 f;
            f = __half22float2(*(__half2*)&q.x); a0 += wjj * f.x; a1 += wjj * f.y;
            f = __half22float2(*(__half2*)&q.y); a2 += wjj * f.x; a3 += wjj * f.y;
        }
    }

#pragma unroll
    for (int o = 16; o; o >>= 1) den += __shfl_xor_sync(0xffffffffu, den, o);
    float inv = 1.f / den;
    float4 b = ((const float4*)bias)[lane];
    float o0 = a0 * inv + b.x, o1 = a1 * inv + b.y;
    float o2 = a2 * inv + b.z, o3 = a3 * inv + b.w;
    o0 = o0 > 0.f ? o0 : 0.f;
    o1 = o1 > 0.f ? o1 : 0.f;
    o2 = o2 > 0.f ? o2 : 0.f;
    o3 = o3 > 0.f ? o3 : 0.f;
    __half2 lo = __floats2half2_rn(o0, o1);
    __half2 hi = __floats2half2_rn(o2, o3);
    ((uint2*)out16)[(size_t)node * 32 + lane] = make_uint2(*(unsigned*)&lo, *(unsigned*)&hi);
}

// ======== F=64, fp16 in, fp32 out (final), unroll x8 ========
__global__ void __launch_bounds__(256) agg64_k(
    const __half* __restrict__ h16,
    const float* __restrict__ as, const float* __restrict__ ad,
    const int* __restrict__ off, const int* __restrict__ srcA,
    const float* __restrict__ bias, float* __restrict__ out) {
    int node = (blockIdx.x * blockDim.x + threadIdx.x) >> 5;
    int lane = threadIdx.x & 31;
    if (node >= NN) return;
    int beg = off[node], end = off[node + 1];
    float adn = ad[node];

    const unsigned int* H = (const unsigned int*)h16;
    float a0 = 0.f, a1 = 0.f, den = 0.f;

    for (int base = beg; base < end; base += 32) {
        int k = base + lane;
        int s = 0;
        float w = 0.f;
        if (k < end) {
            s = srcA[k];
            float e = as[s] + adn;
            e = e > 0.f ? e : NEG * e;
            w = __expf(e);
        }
        den += w;
        int cnt = min(32, end - base);
        int j = 0;
        for (; j + 8 <= cnt; j += 8) {
            int sj[8]; float wj[8]; unsigned q[8];
#pragma unroll
            for (int u = 0; u < 8; u++) {
                sj[u] = __shfl_sync(0xffffffffu, s, j + u);
                wj[u] = __shfl_sync(0xffffffffu, w, j + u);
            }
#pragma unroll
            for (int u = 0; u < 8; u++) q[u] = H[(size_t)sj[u] * 32 + lane];
#pragma unroll
            for (int u = 0; u < 8; u++) {
                float2 f = __half22float2(*(__half2*)&q[u]);
                a0 += wj[u] * f.x; a1 += wj[u] * f.y;
            }
        }
        for (; j < cnt; j++) {
            int   sjj = __shfl_sync(0xffffffffu, s, j);
            float wjj = __shfl_sync(0xffffffffu, w, j);
            unsigned q = H[(size_t)sjj * 32 + lane];
            float2 f = __half22float2(*(__half2*)&q);
            a0 += wjj * f.x; a1 += wjj * f.y;
        }
    }

#pragma unroll
    for (int o = 16; o; o >>= 1) den += __shfl_xor_sync(0xffffffffu, den, o);
    float inv = 1.f / den;
    float2 b = ((const float2*)bias)[lane];
    float2 o2 = make_float2(a0 * inv + b.x, a1 * inv + b.y);
    ((float2*)out)[(size_t)node * 32 + lane] = o2;
}

// ---------------- launch ----------------
extern "C" void kernel_launch(void* const* d_in, const int* in_sizes, int n_in,
                              void* d_out, int out_size) {
    const float* x   = (const float*)d_in[0];
    const int*   ei  = (const int*)d_in[1];
    const float* W1  = (const float*)d_in[2];
    const float* a1s = (const float*)d_in[3];
    const float* a1d = (const float*)d_in[4];
    const float* b1  = (const float*)d_in[5];
    const float* W2  = (const float*)d_in[6];
    const float* a2s = (const float*)d_in[7];
    const float* a2d = (const float*)d_in[8];
    const float* b2  = (const float*)d_in[9];
    float* out = (float*)d_out;

    __half *h1h, *acc1h, *h2h, *w1t, *w2t;
    float *as, *ad;
    int *cnt, *off, *rank, *srcA;
    cudaGetSymbolAddress((void**)&h1h,   g_h1h);
    cudaGetSymbolAddress((void**)&acc1h, g_acc1h);
    cudaGetSymbolAddress((void**)&h2h,   g_h2h);
    cudaGetSymbolAddress((void**)&w1t,   g_w1t);
    cudaGetSymbolAddress((void**)&w2t,   g_w2t);
    cudaGetSymbolAddress((void**)&as,    g_as);
    cudaGetSymbolAddress((void**)&ad,    g_ad);
    cudaGetSymbolAddress((void**)&cnt,   g_cnt);
    cudaGetSymbolAddress((void**)&off,   g_off);
    cudaGetSymbolAddress((void**)&rank,  g_rank);
    cudaGetSymbolAddress((void**)&srcA,  g_srcA);

    const int T = 256;

    // Fork: CSR build (s2) concurrent with convW + gemm1 + alpha1 (stream 0)
    cudaStream_t s2;
    cudaStreamCreateWithFlags(&s2, cudaStreamNonBlocking);
    cudaEvent_t evFork, evJoin;
    cudaEventCreateWithFlags(&evFork, cudaEventDisableTiming);
    cudaEventCreateWithFlags(&evJoin, cudaEventDisableTiming);

    cudaEventRecord(evFork, 0);
    cudaStreamWaitEvent(s2, evFork, 0);

    // ---- CSR build on s2 ----
    cudaMemsetAsync(cnt, 0, NN * sizeof(int), s2);
    hist_k<<<(NE / 8 + T - 1) / T, T, 0, s2>>>(ei, cnt, rank);
    scan_k<<<1, 1024, 0, s2>>>(cnt, off, srcA);
    scatter_k<<<(NE / 8 + T - 1) / T, T, 0, s2>>>(ei, off, rank, srcA);
    cudaEventRecord(evJoin, s2);

    // ---- layer 1 dense part on stream 0 (concurrent with CSR) ----
    convW_k<<<(FIN * FHID + T - 1) / T, T>>>(W1, W2, w1t, w2t);
    hgemm_k<FHID, false><<<(NN + 127) / 128, T>>>(x, w1t, h1h, NN);
    alpha16_k<FHID><<<(NN * 32 + T - 1) / T, T>>>(h1h, a1s, a1d, as, ad);

    cudaStreamWaitEvent(0, evJoin, 0);

    // ---- layer 1 aggregate (fp16 out, relu) ----
    agg128_k<<<(NN * 32 + T - 1) / T, T>>>(h1h, as, ad, off, srcA, b1, acc1h);

    // ---- layer 2 ----
    hgemm_k<FOUT, true><<<(NN + 127) / 128, T>>>(acc1h, w2t, h2h, NN);
    alpha16_k<FOUT><<<(NN * 32 + T - 1) / T, T>>>(h2h, a2s, a2d, as, ad);
    agg64_k<<<(NN * 32 + T - 1) / T, T>>>(h2h, as, ad, off, srcA, b2, out);

    cudaEventDestroy(evFork);
    cudaEventDestroy(evJoin);
    cudaStreamDestroy(s2);
}

// round 10
// speedup vs baseline: 1.4048x; 1.4048x over previous
#include <cuda_runtime.h>
#include <cuda_fp16.h>
#include <math_constants.h>

#define NN   50000
#define NE   800000
#define NET  (NE + NN)          // 850000 edges incl. self loops
#define FIN  128
#define FHID 128
#define FOUT 64
#define NEG  0.2f

// ---------------- scratch (static device globals; no allocation) ----------------
__device__ __half g_h1h[NN * FHID];     // fp16 h layer1
__device__ __half g_acc1h[NN * FHID];   // fp16 layer1 out / layer2 in
__device__ __half g_h2h[NN * FOUT];     // fp16 h layer2
__device__ __half g_w1t[FHID * FIN];    // W1^T fp16  [n][k]
__device__ __half g_w2t[FOUT * FHID];   // W2^T fp16  [n][k]
__device__ float  g_as[NN];
__device__ float  g_ad[NN];
__device__ int    g_cnt[NN];
__device__ int    g_off[NN + 1];
__device__ int    g_rank[NE];
__device__ int    g_srcA[NET];

// ================= mma.m16n8k16 fp16 -> fp32 =================
__device__ __forceinline__ void mma16816(float* c, const unsigned* a,
                                         unsigned b0, unsigned b1) {
    asm volatile(
        "mma.sync.aligned.m16n8k16.row.col.f32.f16.f16.f32 "
        "{%0,%1,%2,%3}, {%4,%5,%6,%7}, {%8,%9}, {%0,%1,%2,%3};\n"
        : "+f"(c[0]), "+f"(c[1]), "+f"(c[2]), "+f"(c[3])
        : "r"(a[0]), "r"(a[1]), "r"(a[2]), "r"(a[3]), "r"(b0), "r"(b1));
}

// ---- convert W1, W2 to fp16 transposed [n][k] ----
__global__ void convW_k(const float* __restrict__ W1, const float* __restrict__ W2,
                        __half* __restrict__ Wt1, __half* __restrict__ Wt2) {
    int i = blockIdx.x * blockDim.x + threadIdx.x;
    if (i < FIN * FHID) {
        int k = i / FHID, n = i % FHID;
        Wt1[n * FIN + k] = __float2half(W1[i]);
    }
    if (i < FHID * FOUT) {
        int k = i / FOUT, n = i % FOUT;
        Wt2[n * FHID + k] = __float2half(W2[i]);
    }
}

// ====== HGEMM: C16[M,BN] = A[M,128] @ Bt^T ; fused alpha logits in epilogue ====
// as_out[r] = C[r,:]·a_src ; ad_out[r] = C[r,:]·a_dst (fp32 accumulators).
// BN=64: one warp owns a full row -> direct store. BN=128: two warps per row ->
// atomicAdd onto pre-zeroed as/ad.
template<int BN, bool AF16>
__global__ void __launch_bounds__(256) hgemm_k(const void* __restrict__ Aptr,
                                               const __half* __restrict__ Bt,  // [BN][128]
                                               __half* __restrict__ C16,
                                               const float* __restrict__ a_src,
                                               const float* __restrict__ a_dst,
                                               float* __restrict__ as_out,
                                               float* __restrict__ ad_out, int M) {
    constexpr int K = 128, BM = 128, BK = 64;
    constexpr int MT = (BN == 128) ? 2 : 1;
    __shared__ __half Ah[BM][BK + 8];
    __shared__ __half Bs[BN][BK + 8];

    const int tid  = threadIdx.x;
    const int wid  = tid >> 5;
    const int lane = tid & 31;
    const int gr   = lane >> 2;
    const int tig  = lane & 3;
    const int row0 = blockIdx.x * BM;

    int warpRow, warpCol;
    if (BN == 128) { warpRow = (wid >> 1) * 32; warpCol = (wid & 1) * 64; }
    else           { warpRow = wid * 16;        warpCol = 0; }

    float acc[MT][8][4];
#pragma unroll
    for (int mi = 0; mi < MT; mi++)
#pragma unroll
        for (int ni = 0; ni < 8; ni++)
#pragma unroll
            for (int j = 0; j < 4; j++) acc[mi][ni][j] = 0.f;

    for (int kc = 0; kc < K; kc += BK) {
        if (AF16) {
#pragma unroll
            for (int i = tid; i < BM * BK / 8; i += 256) {
                int r = i / (BK / 8), c8 = i % (BK / 8);
                uint4 v = make_uint4(0, 0, 0, 0);
                if (row0 + r < M)
                    v = *(const uint4*)((const __half*)Aptr + (size_t)(row0 + r) * K + kc + c8 * 8);
                *(uint4*)&Ah[r][c8 * 8] = v;
            }
        } else {
#pragma unroll
            for (int i = tid; i < BM * BK / 4; i += 256) {
                int r = i / (BK / 4), c4 = i % (BK / 4);
                float4 v = make_float4(0.f, 0.f, 0.f, 0.f);
                if (row0 + r < M)
                    v = *(const float4*)((const float*)Aptr + (size_t)(row0 + r) * K + kc + c4 * 4);
                __half2 h0 = __floats2half2_rn(v.x, v.y);
                __half2 h1 = __floats2half2_rn(v.z, v.w);
                *(uint2*)&Ah[r][c4 * 4] = make_uint2(*(unsigned*)&h0, *(unsigned*)&h1);
            }
        }
#pragma unroll
        for (int i = tid; i < BN * BK / 8; i += 256) {
            int n = i / (BK / 8), c8 = i % (BK / 8);
            *(uint4*)&Bs[n][c8 * 8] = *(const uint4*)(Bt + (size_t)n * K + kc + c8 * 8);
        }
        __syncthreads();

#pragma unroll
        for (int kk = 0; kk < BK; kk += 16) {
            unsigned a[MT][4];
#pragma unroll
            for (int mi = 0; mi < MT; mi++) {
                int r = warpRow + mi * 16 + gr;
                a[mi][0] = *(unsigned*)&Ah[r][kk + tig * 2];
                a[mi][1] = *(unsigned*)&Ah[r + 8][kk + tig * 2];
                a[mi][2] = *(unsigned*)&Ah[r][kk + tig * 2 + 8];
                a[mi][3] = *(unsigned*)&Ah[r + 8][kk + tig * 2 + 8];
            }
#pragma unroll
            for (int ni = 0; ni < 8; ni++) {
                int n = warpCol + ni * 8 + gr;
                unsigned b0 = *(unsigned*)&Bs[n][kk + tig * 2];
                unsigned b1 = *(unsigned*)&Bs[n][kk + tig * 2 + 8];
#pragma unroll
                for (int mi = 0; mi < MT; mi++) mma16816(acc[mi][ni], a[mi], b0, b1);
            }
        }
        __syncthreads();
    }

    // ---- store C16 ----
#pragma unroll
    for (int mi = 0; mi < MT; mi++)
#pragma unroll
        for (int ni = 0; ni < 8; ni++) {
            int r = row0 + warpRow + mi * 16 + gr;
            int c = warpCol + ni * 8 + tig * 2;
            __half2 lo = __floats2half2_rn(acc[mi][ni][0], acc[mi][ni][1]);
            __half2 hi = __floats2half2_rn(acc[mi][ni][2], acc[mi][ni][3]);
            if (r < M)     *(__half2*)&C16[(size_t)r * BN + c] = lo;
            if (r + 8 < M) *(__half2*)&C16[(size_t)(r + 8) * BN + c] = hi;
        }

    // ---- fused alpha: per-row dot with a_src / a_dst ----
#pragma unroll
    for (int mi = 0; mi < MT; mi++) {
        float ssA = 0.f, sdA = 0.f, ssB = 0.f, sdB = 0.f;
#pragma unroll
        for (int ni = 0; ni < 8; ni++) {
            int c = warpCol + ni * 8 + tig * 2;
            float2 sv = *(const float2*)&a_src[c];
            float2 dv = *(const float2*)&a_dst[c];
            ssA += acc[mi][ni][0] * sv.x + acc[mi][ni][1] * sv.y;
            sdA += acc[mi][ni][0] * dv.x + acc[mi][ni][1] * dv.y;
            ssB += acc[mi][ni][2] * sv.x + acc[mi][ni][3] * sv.y;
            sdB += acc[mi][ni][2] * dv.x + acc[mi][ni][3] * dv.y;
        }
        // reduce over the 4 tig lanes (same gr): offsets 2 then 1 stay in-group
#pragma unroll
        for (int o = 2; o; o >>= 1) {
            ssA += __shfl_down_sync(0xffffffffu, ssA, o);
            sdA += __shfl_down_sync(0xffffffffu, sdA, o);
            ssB += __shfl_down_sync(0xffffffffu, ssB, o);
            sdB += __shfl_down_sync(0xffffffffu, sdB, o);
        }
        if (tig == 0) {
            int r = row0 + warpRow + mi * 16 + gr;
            if (BN == 128) {
                if (r < M)     { atomicAdd(&as_out[r], ssA);     atomicAdd(&ad_out[r], sdA); }
                if (r + 8 < M) { atomicAdd(&as_out[r + 8], ssB); atomicAdd(&ad_out[r + 8], sdB); }
            } else {
                if (r < M)     { as_out[r] = ssA;     ad_out[r] = sdA; }
                if (r + 8 < M) { as_out[r + 8] = ssB; ad_out[r + 8] = sdB; }
            }
        }
    }
}

// ================= CSR build (dst-sorted adjacency) =================
// 4 edges/thread; rank = per-dst arrival order
__global__ void hist_k(const int* __restrict__ ei, int* __restrict__ cnt,
                       int* __restrict__ rank) {
    int t = blockIdx.x * blockDim.x + threadIdx.x;
    int idx = t * 4;
    if (idx >= NE) return;
    int4 d = *(const int4*)&ei[NE + idx];
    int r0 = atomicAdd(&cnt[d.x], 1);
    int r1 = atomicAdd(&cnt[d.y], 1);
    int r2 = atomicAdd(&cnt[d.z], 1);
    int r3 = atomicAdd(&cnt[d.w], 1);
    *(int4*)&rank[idx] = make_int4(r0, r1, r2, r3);
}

// single-block scan: off[i+1] = prefix-sum of (cnt[i]+1)
__global__ void __launch_bounds__(1024) scan_k(const int* __restrict__ cnt,
                                               int* __restrict__ off) {
    __shared__ int wsum[32];
    const int tid  = threadIdx.x;
    const int wid  = tid >> 5;
    const int lane = tid & 31;
    int carry = 0;
    if (tid == 0) off[0] = 0;
    for (int base = 0; base < NN; base += 4096) {
        int i0 = base + tid * 4;
        int v0 = 0, v1 = 0, v2 = 0, v3 = 0;
        if (i0 + 3 < NN) {
            int4 c = *(const int4*)&cnt[i0];
            v0 = c.x + 1; v1 = c.y + 1; v2 = c.z + 1; v3 = c.w + 1;
        } else {
            if (i0 + 0 < NN) v0 = cnt[i0 + 0] + 1;
            if (i0 + 1 < NN) v1 = cnt[i0 + 1] + 1;
            if (i0 + 2 < NN) v2 = cnt[i0 + 2] + 1;
            if (i0 + 3 < NN) v3 = cnt[i0 + 3] + 1;
        }
        v1 += v0; v2 += v1; v3 += v2;
        int t = v3;
        int incl = t;
#pragma unroll
        for (int o = 1; o < 32; o <<= 1) {
            int n = __shfl_up_sync(0xffffffffu, incl, o);
            if (lane >= o) incl += n;
        }
        if (lane == 31) wsum[wid] = incl;
        __syncthreads();
        if (wid == 0) {
            int s = wsum[lane];
#pragma unroll
            for (int o = 1; o < 32; o <<= 1) {
                int n = __shfl_up_sync(0xffffffffu, s, o);
                if (lane >= o) s += n;
            }
            wsum[lane] = s;
        }
        __syncthreads();
        int prefix = carry + (wid ? wsum[wid - 1] : 0) + (incl - t);
        if (i0 + 0 < NN) off[i0 + 1] = prefix + v0;
        if (i0 + 1 < NN) off[i0 + 2] = prefix + v1;
        if (i0 + 2 < NN) off[i0 + 3] = prefix + v2;
        if (i0 + 3 < NN) off[i0 + 4] = prefix + v3;
        carry += wsum[31];
        __syncthreads();
    }
}

// self loop occupies slot off[g]
__global__ void self_k(const int* __restrict__ off, int* __restrict__ srcA) {
    int g = blockIdx.x * blockDim.x + threadIdx.x;
    if (g < NN) srcA[off[g]] = g;
}

// atomic-free scatter: position = off[dst] + 1 + rank ; 4 edges/thread
__global__ void scatter_k(const int* __restrict__ ei, const int* __restrict__ off,
                          const int* __restrict__ rank, int* __restrict__ srcA) {
    int t = blockIdx.x * blockDim.x + threadIdx.x;
    int idx = t * 4;
    if (idx >= NE) return;
    int4 s  = *(const int4*)&ei[idx];
    int4 d  = *(const int4*)&ei[NE + idx];
    int4 rk = *(const int4*)&rank[idx];
    srcA[off[d.x] + 1 + rk.x] = s.x;
    srcA[off[d.y] + 1 + rk.y] = s.y;
    srcA[off[d.z] + 1 + rk.z] = s.z;
    srcA[off[d.w] + 1 + rk.w] = s.w;
}

// ======== fused gather+softmax+aggregate, F=128, fp16 in, fp16 out (+relu) =====
__global__ void __launch_bounds__(256) agg128_k(
    const __half* __restrict__ h16,
    const float* __restrict__ as, const float* __restrict__ ad,
    const int* __restrict__ off, const int* __restrict__ srcA,
    const float* __restrict__ bias, __half* __restrict__ out16) {
    int node = (blockIdx.x * blockDim.x + threadIdx.x) >> 5;
    int lane = threadIdx.x & 31;
    if (node >= NN) return;
    int beg = off[node], end = off[node + 1];
    float adn = ad[node];

    const uint2* H = (const uint2*)h16;
    float a0 = 0.f, a1 = 0.f, a2 = 0.f, a3 = 0.f, den = 0.f;

    for (int base = beg; base < end; base += 32) {
        int k = base + lane;
        int s = 0;
        float w = 0.f;
        if (k < end) {
            s = srcA[k];
            float e = as[s] + adn;
            e = e > 0.f ? e : NEG * e;
            w = __expf(e);                  // no max-shift: softmax invariant, |e| small
        }
        den += w;
        int cnt = min(32, end - base);
        int j = 0;
        for (; j + 4 <= cnt; j += 4) {
            int   s0 = __shfl_sync(0xffffffffu, s, j);
            int   s1 = __shfl_sync(0xffffffffu, s, j + 1);
            int   s2 = __shfl_sync(0xffffffffu, s, j + 2);
            int   s3 = __shfl_sync(0xffffffffu, s, j + 3);
            float w0 = __shfl_sync(0xffffffffu, w, j);
            float w1 = __shfl_sync(0xffffffffu, w, j + 1);
            float w2 = __shfl_sync(0xffffffffu, w, j + 2);
            float w3 = __shfl_sync(0xffffffffu, w, j + 3);
            uint2 q0 = H[(size_t)s0 * 32 + lane];
            uint2 q1 = H[(size_t)s1 * 32 + lane];
            uint2 q2 = H[(size_t)s2 * 32 + lane];
            uint2 q3 = H[(size_t)s3 * 32 + lane];
            float2 f;
            f = __half22float2(*(__half2*)&q0.x); a0 += w0 * f.x; a1 += w0 * f.y;
            f = __half22float2(*(__half2*)&q0.y); a2 += w0 * f.x; a3 += w0 * f.y;
            f = __half22float2(*(__half2*)&q1.x); a0 += w1 * f.x; a1 += w1 * f.y;
            f = __half22float2(*(__half2*)&q1.y); a2 += w1 * f.x; a3 += w1 * f.y;
            f = __half22float2(*(__half2*)&q2.x); a0 += w2 * f.x; a1 += w2 * f.y;
            f = __half22float2(*(__half2*)&q2.y); a2 += w2 * f.x; a3 += w2 * f.y;
            f = __half22float2(*(__half2*)&q3.x); a0 += w3 * f.x; a1 += w3 * f.y;
            f = __half22float2(*(__half2*)&q3.y); a2 += w3 * f.x; a3 += w3 * f.y;
        }
        for (; j < cnt; j++) {
            int   sj = __shfl_sync(0xffffffffu, s, j);
            float wj = __shfl_sync(0xffffffffu, w, j);
            uint2 q = H[(size_t)sj * 32 + lane];
            float2 f;
            f = __half22float2(*(__half2*)&q.x); a0 += wj * f.x; a1 += wj * f.y;
            f = __half22float2(*(__half2*)&q.y); a2 += wj * f.x; a3 += wj * f.y;
        }
    }

#pragma unroll
    for (int o = 16; o; o >>= 1) den += __shfl_xor_sync(0xffffffffu, den, o);
    float inv = 1.f / den;
    float4 b = ((const float4*)bias)[lane];
    float o0 = a0 * inv + b.x, o1 = a1 * inv + b.y;
    float o2 = a2 * inv + b.z, o3 = a3 * inv + b.w;
    o0 = o0 > 0.f ? o0 : 0.f;
    o1 = o1 > 0.f ? o1 : 0.f;
    o2 = o2 > 0.f ? o2 : 0.f;
    o3 = o3 > 0.f ? o3 : 0.f;
    __half2 lo = __floats2half2_rn(o0, o1);
    __half2 hi = __floats2half2_rn(o2, o3);
    ((uint2*)out16)[(size_t)node * 32 + lane] = make_uint2(*(unsigned*)&lo, *(unsigned*)&hi);
}

// ======== F=64, fp16 in, fp32 out (final) ========
__global__ void __launch_bounds__(256) agg64_k(
    const __half* __restrict__ h16,
    const float* __restrict__ as, const float* __restrict__ ad,
    const int* __restrict__ off, const int* __restrict__ srcA,
    const float* __restrict__ bias, float* __restrict__ out) {
    int node = (blockIdx.x * blockDim.x + threadIdx.x) >> 5;
    int lane = threadIdx.x & 31;
    if (node >= NN) return;
    int beg = off[node], end = off[node + 1];
    float adn = ad[node];

    const unsigned int* H = (const unsigned int*)h16;
    float a0 = 0.f, a1 = 0.f, den = 0.f;

    for (int base = beg; base < end; base += 32) {
        int k = base + lane;
        int s = 0;
        float w = 0.f;
        if (k < end) {
            s = srcA[k];
            float e = as[s] + adn;
            e = e > 0.f ? e : NEG * e;
            w = __expf(e);
        }
        den += w;
        int cnt = min(32, end - base);
        int j = 0;
        for (; j + 4 <= cnt; j += 4) {
            int   s0 = __shfl_sync(0xffffffffu, s, j);
            int   s1 = __shfl_sync(0xffffffffu, s, j + 1);
            int   s2 = __shfl_sync(0xffffffffu, s, j + 2);
            int   s3 = __shfl_sync(0xffffffffu, s, j + 3);
            float w0 = __shfl_sync(0xffffffffu, w, j);
            float w1 = __shfl_sync(0xffffffffu, w, j + 1);
            float w2 = __shfl_sync(0xffffffffu, w, j + 2);
            float w3 = __shfl_sync(0xffffffffu, w, j + 3);
            unsigned int q0 = H[(size_t)s0 * 32 + lane];
            unsigned int q1 = H[(size_t)s1 * 32 + lane];
            unsigned int q2 = H[(size_t)s2 * 32 + lane];
            unsigned int q3 = H[(size_t)s3 * 32 + lane];
            float2 f;
            f = __half22float2(*(__half2*)&q0); a0 += w0 * f.x; a1 += w0 * f.y;
            f = __half22float2(*(__half2*)&q1); a0 += w1 * f.x; a1 += w1 * f.y;
            f = __half22float2(*(__half2*)&q2); a0 += w2 * f.x; a1 += w2 * f.y;
            f = __half22float2(*(__half2*)&q3); a0 += w3 * f.x; a1 += w3 * f.y;
        }
        for (; j < cnt; j++) {
            int   sj = __shfl_sync(0xffffffffu, s, j);
            float wj = __shfl_sync(0xffffffffu, w, j);
            unsigned int q = H[(size_t)sj * 32 + lane];
            float2 f = __half22float2(*(__half2*)&q);
            a0 += wj * f.x; a1 += wj * f.y;
        }
    }

#pragma unroll
    for (int o = 16; o; o >>= 1) den += __shfl_xor_sync(0xffffffffu, den, o);
    float inv = 1.f / den;
    float2 b = ((const float2*)bias)[lane];
    float2 o2 = make_float2(a0 * inv + b.x, a1 * inv + b.y);
    ((float2*)out)[(size_t)node * 32 + lane] = o2;
}

// ---------------- launch ----------------
extern "C" void kernel_launch(void* const* d_in, const int* in_sizes, int n_in,
                              void* d_out, int out_size) {
    const float* x   = (const float*)d_in[0];
    const int*   ei  = (const int*)d_in[1];
    const float* W1  = (const float*)d_in[2];
    const float* a1s = (const float*)d_in[3];
    const float* a1d = (const float*)d_in[4];
    const float* b1  = (const float*)d_in[5];
    const float* W2  = (const float*)d_in[6];
    const float* a2s = (const float*)d_in[7];
    const float* a2d = (const float*)d_in[8];
    const float* b2  = (const float*)d_in[9];
    float* out = (float*)d_out;

    __half *h1h, *acc1h, *h2h, *w1t, *w2t;
    float *as, *ad;
    int *cnt, *off, *rank, *srcA;
    cudaGetSymbolAddress((void**)&h1h,   g_h1h);
    cudaGetSymbolAddress((void**)&acc1h, g_acc1h);
    cudaGetSymbolAddress((void**)&h2h,   g_h2h);
    cudaGetSymbolAddress((void**)&w1t,   g_w1t);
    cudaGetSymbolAddress((void**)&w2t,   g_w2t);
    cudaGetSymbolAddress((void**)&as,    g_as);
    cudaGetSymbolAddress((void**)&ad,    g_ad);
    cudaGetSymbolAddress((void**)&cnt,   g_cnt);
    cudaGetSymbolAddress((void**)&off,   g_off);
    cudaGetSymbolAddress((void**)&rank,  g_rank);
    cudaGetSymbolAddress((void**)&srcA,  g_srcA);

    const int T = 256;

    // Fork: CSR build (s2) concurrent with convW + gemm1 (stream 0)
    cudaStream_t s2;
    cudaStreamCreateWithFlags(&s2, cudaStreamNonBlocking);
    cudaEvent_t evFork, evJoin;
    cudaEventCreateWithFlags(&evFork, cudaEventDisableTiming);
    cudaEventCreateWithFlags(&evJoin, cudaEventDisableTiming);

    cudaEventRecord(evFork, 0);
    cudaStreamWaitEvent(s2, evFork, 0);

    // ---- CSR build on s2 ----
    cudaMemsetAsync(cnt, 0, NN * sizeof(int), s2);
    hist_k<<<(NE / 4 + T - 1) / T, T, 0, s2>>>(ei, cnt, rank);
    scan_k<<<1, 1024, 0, s2>>>(cnt, off);
    self_k<<<(NN + T - 1) / T, T, 0, s2>>>(off, srcA);
    scatter_k<<<(NE / 4 + T - 1) / T, T, 0, s2>>>(ei, off, rank, srcA);
    cudaEventRecord(evJoin, s2);

    // ---- layer 1 dense part on stream 0 (concurrent with CSR) ----
    cudaMemsetAsync(as, 0, NN * sizeof(float));   // gemm1 alpha uses atomicAdd
    cudaMemsetAsync(ad, 0, NN * sizeof(float));
    convW_k<<<(FIN * FHID + T - 1) / T, T>>>(W1, W2, w1t, w2t);
    hgemm_k<FHID, false><<<(NN + 127) / 128, T>>>(x, w1t, h1h, a1s, a1d, as, ad, NN);

    cudaStreamWaitEvent(0, evJoin, 0);

    // ---- layer 1 aggregate (fp16 out, relu) ----
    agg128_k<<<(NN * 32 + T - 1) / T, T>>>(h1h, as, ad, off, srcA, b1, acc1h);

    // ---- layer 2 (alpha fused; BN=64 writes as/ad directly, no zeroing) ----
    hgemm_k<FOUT, true><<<(NN + 127) / 128, T>>>(acc1h, w2t, h2h, a2s, a2d, as, ad, NN);
    agg64_k<<<(NN * 32 + T - 1) / T, T>>>(h2h, as, ad, off, srcA, b2, out);

    cudaEventDestroy(evFork);
    cudaEventDestroy(evJoin);
    cudaStreamDestroy(s2);
}

// round 12
// speedup vs baseline: 1.5103x; 1.0751x over previous
#include <cuda_runtime.h>
#include <cuda_fp16.h>
#include <math_constants.h>

#define NN   50000
#define NE   800000
#define NET  (NE + NN)          // 850000 edges incl. self loops
#define FIN  128
#define FHID 128
#define FOUT 64
#define NEG  0.2f

// ---------------- scratch (static device globals; no allocation) ----------------
__device__ __half g_h1h[NN * FHID];     // fp16 h layer1
__device__ __half g_acc1h[NN * FHID];   // fp16 layer1 out / layer2 in
__device__ __half g_h2h[NN * FOUT];     // fp16 h layer2
__device__ __half g_w1t[FHID * FIN];    // W1^T fp16  [n][k]
__device__ __half g_w2t[FOUT * FHID];   // W2^T fp16  [n][k]
__device__ float  g_as[NN];
__device__ float  g_ad[NN];
__device__ int    g_cnt[NN];
__device__ int    g_off[NN + 1];
__device__ int    g_rank[NE];
__device__ int    g_srcA[NET];

// ================= mma.m16n8k16 fp16 -> fp32 =================
__device__ __forceinline__ void mma16816(float* c, const unsigned* a,
                                         unsigned b0, unsigned b1) {
    asm volatile(
        "mma.sync.aligned.m16n8k16.row.col.f32.f16.f16.f32 "
        "{%0,%1,%2,%3}, {%4,%5,%6,%7}, {%8,%9}, {%0,%1,%2,%3};\n"
        : "+f"(c[0]), "+f"(c[1]), "+f"(c[2]), "+f"(c[3])
        : "r"(a[0]), "r"(a[1]), "r"(a[2]), "r"(a[3]), "r"(b0), "r"(b1));
}

// ---- convert W1, W2 to fp16 transposed [n][k] ----
__global__ void convW_k(const float* __restrict__ W1, const float* __restrict__ W2,
                        __half* __restrict__ Wt1, __half* __restrict__ Wt2) {
    int i = blockIdx.x * blockDim.x + threadIdx.x;
    if (i < FIN * FHID) {
        int k = i / FHID, n = i % FHID;
        Wt1[n * FIN + k] = __float2half(W1[i]);
    }
    if (i < FHID * FOUT) {
        int k = i / FOUT, n = i % FOUT;
        Wt2[n * FHID + k] = __float2half(W2[i]);
    }
}

// ====== HGEMM: C16[M,BN] = A[M,128] @ Bt^T ; fused alpha logits in epilogue ====
template<int BN, bool AF16>
__global__ void __launch_bounds__(256) hgemm_k(const void* __restrict__ Aptr,
                                               const __half* __restrict__ Bt,  // [BN][128]
                                               __half* __restrict__ C16,
                                               const float* __restrict__ a_src,
                                               const float* __restrict__ a_dst,
                                               float* __restrict__ as_out,
                                               float* __restrict__ ad_out, int M) {
    constexpr int K = 128, BM = 128, BK = 64;
    constexpr int MT = (BN == 128) ? 2 : 1;
    __shared__ __half Ah[BM][BK + 8];
    __shared__ __half Bs[BN][BK + 8];

    const int tid  = threadIdx.x;
    const int wid  = tid >> 5;
    const int lane = tid & 31;
    const int gr   = lane >> 2;
    const int tig  = lane & 3;
    const int row0 = blockIdx.x * BM;

    int warpRow, warpCol;
    if (BN == 128) { warpRow = (wid >> 1) * 32; warpCol = (wid & 1) * 64; }
    else           { warpRow = wid * 16;        warpCol = 0; }

    float acc[MT][8][4];
#pragma unroll
    for (int mi = 0; mi < MT; mi++)
#pragma unroll
        for (int ni = 0; ni < 8; ni++)
#pragma unroll
            for (int j = 0; j < 4; j++) acc[mi][ni][j] = 0.f;

    for (int kc = 0; kc < K; kc += BK) {
        if (AF16) {
#pragma unroll
            for (int i = tid; i < BM * BK / 8; i += 256) {
                int r = i / (BK / 8), c8 = i % (BK / 8);
                uint4 v = make_uint4(0, 0, 0, 0);
                if (row0 + r < M)
                    v = *(const uint4*)((const __half*)Aptr + (size_t)(row0 + r) * K + kc + c8 * 8);
                *(uint4*)&Ah[r][c8 * 8] = v;
            }
        } else {
#pragma unroll
            for (int i = tid; i < BM * BK / 4; i += 256) {
                int r = i / (BK / 4), c4 = i % (BK / 4);
                float4 v = make_float4(0.f, 0.f, 0.f, 0.f);
                if (row0 + r < M)
                    v = *(const float4*)((const float*)Aptr + (size_t)(row0 + r) * K + kc + c4 * 4);
                __half2 h0 = __floats2half2_rn(v.x, v.y);
                __half2 h1 = __floats2half2_rn(v.z, v.w);
                *(uint2*)&Ah[r][c4 * 4] = make_uint2(*(unsigned*)&h0, *(unsigned*)&h1);
            }
        }
#pragma unroll
        for (int i = tid; i < BN * BK / 8; i += 256) {
            int n = i / (BK / 8), c8 = i % (BK / 8);
            *(uint4*)&Bs[n][c8 * 8] = *(const uint4*)(Bt + (size_t)n * K + kc + c8 * 8);
        }
        __syncthreads();

#pragma unroll
        for (int kk = 0; kk < BK; kk += 16) {
            unsigned a[MT][4];
#pragma unroll
            for (int mi = 0; mi < MT; mi++) {
                int r = warpRow + mi * 16 + gr;
                a[mi][0] = *(unsigned*)&Ah[r][kk + tig * 2];
                a[mi][1] = *(unsigned*)&Ah[r + 8][kk + tig * 2];
                a[mi][2] = *(unsigned*)&Ah[r][kk + tig * 2 + 8];
                a[mi][3] = *(unsigned*)&Ah[r + 8][kk + tig * 2 + 8];
            }
#pragma unroll
            for (int ni = 0; ni < 8; ni++) {
                int n = warpCol + ni * 8 + gr;
                unsigned b0 = *(unsigned*)&Bs[n][kk + tig * 2];
                unsigned b1 = *(unsigned*)&Bs[n][kk + tig * 2 + 8];
#pragma unroll
                for (int mi = 0; mi < MT; mi++) mma16816(acc[mi][ni], a[mi], b0, b1);
            }
        }
        __syncthreads();
    }

    // ---- store C16 ----
#pragma unroll
    for (int mi = 0; mi < MT; mi++)
#pragma unroll
        for (int ni = 0; ni < 8; ni++) {
            int r = row0 + warpRow + mi * 16 + gr;
            int c = warpCol + ni * 8 + tig * 2;
            __half2 lo = __floats2half2_rn(acc[mi][ni][0], acc[mi][ni][1]);
            __half2 hi = __floats2half2_rn(acc[mi][ni][2], acc[mi][ni][3]);
            if (r < M)     *(__half2*)&C16[(size_t)r * BN + c] = lo;
            if (r + 8 < M) *(__half2*)&C16[(size_t)(r + 8) * BN + c] = hi;
        }

    // ---- fused alpha: per-row dot with a_src / a_dst ----
#pragma unroll
    for (int mi = 0; mi < MT; mi++) {
        float ssA = 0.f, sdA = 0.f, ssB = 0.f, sdB = 0.f;
#pragma unroll
        for (int ni = 0; ni < 8; ni++) {
            int c = warpCol + ni * 8 + tig * 2;
            float2 sv = *(const float2*)&a_src[c];
            float2 dv = *(const float2*)&a_dst[c];
            ssA += acc[mi][ni][0] * sv.x + acc[mi][ni][1] * sv.y;
            sdA += acc[mi][ni][0] * dv.x + acc[mi][ni][1] * dv.y;
            ssB += acc[mi][ni][2] * sv.x + acc[mi][ni][3] * sv.y;
            sdB += acc[mi][ni][2] * dv.x + acc[mi][ni][3] * dv.y;
        }
#pragma unroll
        for (int o = 2; o; o >>= 1) {
            ssA += __shfl_down_sync(0xffffffffu, ssA, o);
            sdA += __shfl_down_sync(0xffffffffu, sdA, o);
            ssB += __shfl_down_sync(0xffffffffu, ssB, o);
            sdB += __shfl_down_sync(0xffffffffu, sdB, o);
        }
        if (tig == 0) {
            int r = row0 + warpRow + mi * 16 + gr;
            if (BN == 128) {
                if (r < M)     { atomicAdd(&as_out[r], ssA);     atomicAdd(&ad_out[r], sdA); }
                if (r + 8 < M) { atomicAdd(&as_out[r + 8], ssB); atomicAdd(&ad_out[r + 8], sdB); }
            } else {
                if (r < M)     { as_out[r] = ssA;     ad_out[r] = sdA; }
                if (r + 8 < M) { as_out[r + 8] = ssB; ad_out[r + 8] = sdB; }
            }
        }
    }
}

// ================= CSR build (dst-sorted adjacency) =================
__global__ void hist_k(const int* __restrict__ ei, int* __restrict__ cnt,
                       int* __restrict__ rank) {
    int t = blockIdx.x * blockDim.x + threadIdx.x;
    int idx = t * 4;
    if (idx >= NE) return;
    int4 d = *(const int4*)&ei[NE + idx];
    int r0 = atomicAdd(&cnt[d.x], 1);
    int r1 = atomicAdd(&cnt[d.y], 1);
    int r2 = atomicAdd(&cnt[d.z], 1);
    int r3 = atomicAdd(&cnt[d.w], 1);
    *(int4*)&rank[idx] = make_int4(r0, r1, r2, r3);
}

// single-block scan: off[i+1] = prefix-sum of (cnt[i]+1)
__global__ void __launch_bounds__(1024) scan_k(const int* __restrict__ cnt,
                                               int* __restrict__ off) {
    __shared__ int wsum[32];
    const int tid  = threadIdx.x;
    const int wid  = tid >> 5;
    const int lane = tid & 31;
    int carry = 0;
    if (tid == 0) off[0] = 0;
    for (int base = 0; base < NN; base += 4096) {
        int i0 = base + tid * 4;
        int v0 = 0, v1 = 0, v2 = 0, v3 = 0;
        if (i0 + 3 < NN) {
            int4 c = *(const int4*)&cnt[i0];
            v0 = c.x + 1; v1 = c.y + 1; v2 = c.z + 1; v3 = c.w + 1;
        } else {
            if (i0 + 0 < NN) v0 = cnt[i0 + 0] + 1;
            if (i0 + 1 < NN) v1 = cnt[i0 + 1] + 1;
            if (i0 + 2 < NN) v2 = cnt[i0 + 2] + 1;
            if (i0 + 3 < NN) v3 = cnt[i0 + 3] + 1;
        }
        v1 += v0; v2 += v1; v3 += v2;
        int t = v3;
        int incl = t;
#pragma unroll
        for (int o = 1; o < 32; o <<= 1) {
            int n = __shfl_up_sync(0xffffffffu, incl, o);
            if (lane >= o) incl += n;
        }
        if (lane == 31) wsum[wid] = incl;
        __syncthreads();
        if (wid == 0) {
            int s = wsum[lane];
#pragma unroll
            for (int o = 1; o < 32; o <<= 1) {
                int n = __shfl_up_sync(0xffffffffu, s, o);
                if (lane >= o) s += n;
            }
            wsum[lane] = s;
        }
        __syncthreads();
        int prefix = carry + (wid ? wsum[wid - 1] : 0) + (incl - t);
        if (i0 + 0 < NN) off[i0 + 1] = prefix + v0;
        if (i0 + 1 < NN) off[i0 + 2] = prefix + v1;
        if (i0 + 2 < NN) off[i0 + 3] = prefix + v2;
        if (i0 + 3 < NN) off[i0 + 4] = prefix + v3;
        carry += wsum[31];
        __syncthreads();
    }
}

// atomic-free scatter (4 edges/thread) + fused self-loop placement
__global__ void scatter_k(const int* __restrict__ ei, const int* __restrict__ off,
                          const int* __restrict__ rank, int* __restrict__ srcA) {
    int t = blockIdx.x * blockDim.x + threadIdx.x;
    if (t < NN) srcA[off[t]] = t;            // self loop occupies slot off[t]
    int idx = t * 4;
    if (idx >= NE) return;
    int4 s  = *(const int4*)&ei[idx];
    int4 d  = *(const int4*)&ei[NE + idx];
    int4 rk = *(const int4*)&rank[idx];
    srcA[off[d.x] + 1 + rk.x] = s.x;
    srcA[off[d.y] + 1 + rk.y] = s.y;
    srcA[off[d.z] + 1 + rk.z] = s.z;
    srcA[off[d.w] + 1 + rk.w] = s.w;
}

// ======== fused gather+softmax+aggregate, F=128 ========
// Half-warp per row: 16 lanes x uint4 = full 128-half row per LDG.128;
// warp processes 2 edges per load instruction (half 0: edges j..j+3, half 1: j+4..j+7).
__global__ void __launch_bounds__(256) agg128_k(
    const __half* __restrict__ h16,
    const float* __restrict__ as, const float* __restrict__ ad,
    const int* __restrict__ off, const int* __restrict__ srcA,
    const float* __restrict__ bias, __half* __restrict__ out16) {
    int node = (blockIdx.x * blockDim.x + threadIdx.x) >> 5;
    int lane = threadIdx.x & 31;
    if (node >= NN) return;
    int beg = off[node], end = off[node + 1];
    float adn = ad[node];
    const int half  = lane >> 4;
    const int flane = lane & 15;

    const uint4* H = (const uint4*)h16;     // 16 uint4 per row
    float acc[8];
#pragma unroll
    for (int i = 0; i < 8; i++) acc[i] = 0.f;
    float den = 0.f;

    for (int base = beg; base < end; base += 32) {
        int k = base + lane;
        int s = 0;
        float w = 0.f;
        if (k < end) {
            s = srcA[k];
            float e = as[s] + adn;
            e = e > 0.f ? e : NEG * e;
            w = __expf(e);                  // no max-shift: softmax invariant, |e| small
        }
        den += w;
        int cnt = min(32, end - base);
        for (int j = 0; j < cnt; j += 8) {
            int su[4]; float wu[4];
#pragma unroll
            for (int u = 0; u < 4; u++) {
                int idx = j + half * 4 + u;              // <= 31 always
                int   sv = __shfl_sync(0xffffffffu, s, idx);
                float wv = __shfl_sync(0xffffffffu, w, idx);
                bool ok = idx < cnt;
                su[u] = ok ? sv : 0;
                wu[u] = ok ? wv : 0.f;
            }
            uint4 q0 = H[(size_t)su[0] * 16 + flane];
            uint4 q1 = H[(size_t)su[1] * 16 + flane];
            uint4 q2 = H[(size_t)su[2] * 16 + flane];
            uint4 q3 = H[(size_t)su[3] * 16 + flane];
#pragma unroll
            for (int u = 0; u < 4; u++) {
                uint4 q = (u == 0) ? q0 : (u == 1) ? q1 : (u == 2) ? q2 : q3;
                float wv = wu[u];
                float2 f;
                f = __half22float2(*(__half2*)&q.x); acc[0] += wv * f.x; acc[1] += wv * f.y;
                f = __half22float2(*(__half2*)&q.y); acc[2] += wv * f.x; acc[3] += wv * f.y;
                f = __half22float2(*(__half2*)&q.z); acc[4] += wv * f.x; acc[5] += wv * f.y;
                f = __half22float2(*(__half2*)&q.w); acc[6] += wv * f.x; acc[7] += wv * f.y;
            }
        }
    }

    // combine the two half-warps (same feature columns, different edges)
#pragma unroll
    for (int i = 0; i < 8; i++) acc[i] += __shfl_xor_sync(0xffffffffu, acc[i], 16);
#pragma unroll
    for (int o = 16; o; o >>= 1) den += __shfl_xor_sync(0xffffffffu, den, o);
    float inv = 1.f / den;

    if (half == 0) {
        float4 b0 = ((const float4*)bias)[flane * 2];
        float4 b1 = ((const float4*)bias)[flane * 2 + 1];
        float o0 = acc[0] * inv + b0.x, o1 = acc[1] * inv + b0.y;
        float o2 = acc[2] * inv + b0.z, o3 = acc[3] * inv + b0.w;
        float o4 = acc[4] * inv + b1.x, o5 = acc[5] * inv + b1.y;
        float o6 = acc[6] * inv + b1.z, o7 = acc[7] * inv + b1.w;
        o0 = o0 > 0.f ? o0 : 0.f; o1 = o1 > 0.f ? o1 : 0.f;
        o2 = o2 > 0.f ? o2 : 0.f; o3 = o3 > 0.f ? o3 : 0.f;
        o4 = o4 > 0.f ? o4 : 0.f; o5 = o5 > 0.f ? o5 : 0.f;
        o6 = o6 > 0.f ? o6 : 0.f; o7 = o7 > 0.f ? o7 : 0.f;
        __half2 p0 = __floats2half2_rn(o0, o1);
        __half2 p1 = __floats2half2_rn(o2, o3);
        __half2 p2 = __floats2half2_rn(o4, o5);
        __half2 p3 = __floats2half2_rn(o6, o7);
        ((uint4*)out16)[(size_t)node * 16 + flane] =
            make_uint4(*(unsigned*)&p0, *(unsigned*)&p1, *(unsigned*)&p2, *(unsigned*)&p3);
    }
}

// ======== F=64, same half-warp scheme (uint2 per lane), fp32 out ========
__global__ void __launch_bounds__(256) agg64_k(
    const __half* __restrict__ h16,
    const float* __restrict__ as, const float* __restrict__ ad,
    const int* __restrict__ off, const int* __restrict__ srcA,
    const float* __restrict__ bias, float* __restrict__ out) {
    int node = (blockIdx.x * blockDim.x + threadIdx.x) >> 5;
    int lane = threadIdx.x & 31;
    if (node >= NN) return;
    int beg = off[node], end = off[node + 1];
    float adn = ad[node];
    const int half  = lane >> 4;
    const int flane = lane & 15;

    const uint2* H = (const uint2*)h16;     // 16 uint2 per row
    float acc[4];
#pragma unroll
    for (int i = 0; i < 4; i++) acc[i] = 0.f;
    float den = 0.f;

    for (int base = beg; base < end; base += 32) {
        int k = base + lane;
        int s = 0;
        float w = 0.f;
        if (k < end) {
            s = srcA[k];
            float e = as[s] + adn;
            e = e > 0.f ? e : NEG * e;
            w = __expf(e);
        }
        den += w;
        int cnt = min(32, end - base);
        for (int j = 0; j < cnt; j += 8) {
            int su[4]; float wu[4];
#pragma unroll
            for (int u = 0; u < 4; u++) {
                int idx = j + half * 4 + u;
                int   sv = __shfl_sync(0xffffffffu, s, idx);
                float wv = __shfl_sync(0xffffffffu, w, idx);
                bool ok = idx < cnt;
                su[u] = ok ? sv : 0;
                wu[u] = ok ? wv : 0.f;
            }
            uint2 q0 = H[(size_t)su[0] * 16 + flane];
            uint2 q1 = H[(size_t)su[1] * 16 + flane];
            uint2 q2 = H[(size_t)su[2] * 16 + flane];
            uint2 q3 = H[(size_t)su[3] * 16 + flane];
#pragma unroll
            for (int u = 0; u < 4; u++) {
                uint2 q = (u == 0) ? q0 : (u == 1) ? q1 : (u == 2) ? q2 : q3;
                float wv = wu[u];
                float2 f;
                f = __half22float2(*(__half2*)&q.x); acc[0] += wv * f.x; acc[1] += wv * f.y;
                f = __half22float2(*(__half2*)&q.y); acc[2] += wv * f.x; acc[3] += wv * f.y;
            }
        }
    }

#pragma unroll
    for (int i = 0; i < 4; i++) acc[i] += __shfl_xor_sync(0xffffffffu, acc[i], 16);
#pragma unroll
    for (int o = 16; o; o >>= 1) den += __shfl_xor_sync(0xffffffffu, den, o);
    float inv = 1.f / den;

    if (half == 0) {
        float4 b = ((const float4*)bias)[flane];
        float4 o4 = make_float4(acc[0] * inv + b.x, acc[1] * inv + b.y,
                                acc[2] * inv + b.z, acc[3] * inv + b.w);
        ((float4*)out)[(size_t)node * 16 + flane] = o4;
    }
}

// ---------------- launch ----------------
extern "C" void kernel_launch(void* const* d_in, const int* in_sizes, int n_in,
                              void* d_out, int out_size) {
    const float* x   = (const float*)d_in[0];
    const int*   ei  = (const int*)d_in[1];
    const float* W1  = (const float*)d_in[2];
    const float* a1s = (const float*)d_in[3];
    const float* a1d = (const float*)d_in[4];
    const float* b1  = (const float*)d_in[5];
    const float* W2  = (const float*)d_in[6];
    const float* a2s = (const float*)d_in[7];
    const float* a2d = (const float*)d_in[8];
    const float* b2  = (const float*)d_in[9];
    float* out = (float*)d_out;

    __half *h1h, *acc1h, *h2h, *w1t, *w2t;
    float *as, *ad;
    int *cnt, *off, *rank, *srcA;
    cudaGetSymbolAddress((void**)&h1h,   g_h1h);
    cudaGetSymbolAddress((void**)&acc1h, g_acc1h);
    cudaGetSymbolAddress((void**)&h2h,   g_h2h);
    cudaGetSymbolAddress((void**)&w1t,   g_w1t);
    cudaGetSymbolAddress((void**)&w2t,   g_w2t);
    cudaGetSymbolAddress((void**)&as,    g_as);
    cudaGetSymbolAddress((void**)&ad,    g_ad);
    cudaGetSymbolAddress((void**)&cnt,   g_cnt);
    cudaGetSymbolAddress((void**)&off,   g_off);
    cudaGetSymbolAddress((void**)&rank,  g_rank);
    cudaGetSymbolAddress((void**)&srcA,  g_srcA);

    const int T = 256;

    // Fork: CSR build (s2) concurrent with convW + gemm1 (stream 0)
    cudaStream_t s2;
    cudaStreamCreateWithFlags(&s2, cudaStreamNonBlocking);
    cudaEvent_t evFork, evJoin;
    cudaEventCreateWithFlags(&evFork, cudaEventDisableTiming);
    cudaEventCreateWithFlags(&evJoin, cudaEventDisableTiming);

    cudaEventRecord(evFork, 0);
    cudaStreamWaitEvent(s2, evFork, 0);

    // ---- CSR build on s2 ----
    cudaMemsetAsync(cnt, 0, NN * sizeof(int), s2);
    hist_k<<<(NE / 4 + T - 1) / T, T, 0, s2>>>(ei, cnt, rank);
    scan_k<<<1, 1024, 0, s2>>>(cnt, off);
    scatter_k<<<(NE / 4 + T - 1) / T, T, 0, s2>>>(ei, off, rank, srcA);
    cudaEventRecord(evJoin, s2);

    // ---- layer 1 dense part on stream 0 (concurrent with CSR) ----
    cudaMemsetAsync(as, 0, NN * sizeof(float));   // gemm1 alpha uses atomicAdd
    cudaMemsetAsync(ad, 0, NN * sizeof(float));
    convW_k<<<(FIN * FHID + T - 1) / T, T>>>(W1, W2, w1t, w2t);
    hgemm_k<FHID, false><<<(NN + 127) / 128, T>>>(x, w1t, h1h, a1s, a1d, as, ad, NN);

    cudaStreamWaitEvent(0, evJoin, 0);

    // ---- layer 1 aggregate (fp16 out, relu) ----
    agg128_k<<<(NN * 32 + T - 1) / T, T>>>(h1h, as, ad, off, srcA, b1, acc1h);

    // ---- layer 2 (alpha fused; BN=64 writes as/ad directly, no zeroing) ----
    hgemm_k<FOUT, true><<<(NN + 127) / 128, T>>>(acc1h, w2t, h2h, a2s, a2d, as, ad, NN);
    agg64_k<<<(NN * 32 + T - 1) / T, T>>>(h2h, as, ad, off, srcA, b2, out);

    cudaEventDestroy(evFork);
    cudaEventDestroy(evJoin);
    cudaStreamDestroy(s2);
}